// round 1
// baseline (speedup 1.0000x reference)
#include <cuda_runtime.h>
#include <math.h>

#define Bsz 16
#define Qs  64
#define Ns  16384
#define Ds  128

// ---------------------------------------------------------------------------
// Kernel 1: logits[b][q][n] = sum_d qv[b][q][d] * A[b][n][d]
// grid (Ns/128, Bsz), block 256. Output tile per block: 64(q) x 128(n).
// ---------------------------------------------------------------------------
__global__ void k_logits(const float* __restrict__ qv,
                         const float* __restrict__ A,
                         float* __restrict__ logits) {
    const int b  = blockIdx.y;
    const int n0 = blockIdx.x * 128;

    __shared__ __align__(16) float sQ[32][68];    // [k][q], padded
    __shared__ __align__(16) float sA[32][132];   // [k][n], padded

    const int tid = threadIdx.x;
    const int ty  = tid >> 4;       // 0..15
    const int tx  = tid & 15;       // 0..15
    const int qb  = ty * 4;
    const int nb  = tx * 8;

    float acc[4][8];
    #pragma unroll
    for (int i = 0; i < 4; i++)
        #pragma unroll
        for (int j = 0; j < 8; j++) acc[i][j] = 0.f;

    const float* qbase = qv + (size_t)b * Qs * Ds;
    const float* abase = A  + ((size_t)b * Ns + n0) * Ds;

    for (int kk = 0; kk < Ds; kk += 32) {
        // Load Q tile: 64 rows x 32 cols, transposed into sQ[k][q]
        #pragma unroll
        for (int t = 0; t < 2; t++) {
            int f   = tid + t * 256;       // 0..511 float4s
            int row = f >> 3;              // 0..63
            int c4  = f & 7;               // 0..7
            float4 v = *(const float4*)(qbase + row * Ds + kk + c4 * 4);
            sQ[c4 * 4 + 0][row] = v.x;
            sQ[c4 * 4 + 1][row] = v.y;
            sQ[c4 * 4 + 2][row] = v.z;
            sQ[c4 * 4 + 3][row] = v.w;
        }
        // Load A tile: 128 rows x 32 cols, transposed into sA[k][n]
        #pragma unroll
        for (int t = 0; t < 4; t++) {
            int f   = tid + t * 256;       // 0..1023 float4s
            int row = f >> 3;              // 0..127
            int c4  = f & 7;               // 0..7
            float4 v = *(const float4*)(abase + row * Ds + kk + c4 * 4);
            sA[c4 * 4 + 0][row] = v.x;
            sA[c4 * 4 + 1][row] = v.y;
            sA[c4 * 4 + 2][row] = v.z;
            sA[c4 * 4 + 3][row] = v.w;
        }
        __syncthreads();

        #pragma unroll
        for (int k = 0; k < 32; k++) {
            float4 aq = *(const float4*)&sQ[k][qb];
            float4 a0 = *(const float4*)&sA[k][nb];
            float4 a1 = *(const float4*)&sA[k][nb + 4];
            float qr[4] = {aq.x, aq.y, aq.z, aq.w};
            float ar[8] = {a0.x, a0.y, a0.z, a0.w, a1.x, a1.y, a1.z, a1.w};
            #pragma unroll
            for (int i = 0; i < 4; i++)
                #pragma unroll
                for (int j = 0; j < 8; j++)
                    acc[i][j] = fmaf(qr[i], ar[j], acc[i][j]);
        }
        __syncthreads();
    }

    // Write: logits[b][qb+i][n0+nb+j]
    float* lrow = logits + ((size_t)b * Qs + qb) * Ns + n0 + nb;
    #pragma unroll
    for (int i = 0; i < 4; i++) {
        float4 w0 = make_float4(acc[i][0], acc[i][1], acc[i][2], acc[i][3]);
        float4 w1 = make_float4(acc[i][4], acc[i][5], acc[i][6], acc[i][7]);
        *(float4*)(lrow + (size_t)i * Ns)     = w0;
        *(float4*)(lrow + (size_t)i * Ns + 4) = w1;
    }
}

// ---------------------------------------------------------------------------
// Kernel 2: masked softmax over N per (b,q) row.
// grid Bsz*Qs, block 256. Each thread holds 64 elements in registers.
// ---------------------------------------------------------------------------
__global__ void k_softmax(const float* __restrict__ logits,
                          const int* __restrict__ node_nums,
                          float* __restrict__ prob) {
    const int bq  = blockIdx.x;
    const int b   = bq >> 6;            // Qs = 64
    const int nn  = node_nums[b];
    const int tid = threadIdx.x;

    const float* row = logits + (size_t)bq * Ns;
    float v[64];
    #pragma unroll
    for (int i = 0; i < 64; i++) v[i] = row[tid + i * 256];

    // --- max over valid ---
    float m = -INFINITY;
    #pragma unroll
    for (int i = 0; i < 64; i++) {
        int n = tid + i * 256;
        if (n < nn) m = fmaxf(m, v[i]);
    }
    __shared__ float redm[8];
    __shared__ float reds[8];
    #pragma unroll
    for (int o = 16; o > 0; o >>= 1)
        m = fmaxf(m, __shfl_xor_sync(0xffffffffu, m, o));
    if ((tid & 31) == 0) redm[tid >> 5] = m;
    __syncthreads();
    {
        float t = redm[0];
        #pragma unroll
        for (int w = 1; w < 8; w++) t = fmaxf(t, redm[w]);
        m = t;
    }

    // --- exp + sum ---
    float s = 0.f;
    #pragma unroll
    for (int i = 0; i < 64; i++) {
        int n = tid + i * 256;
        float e = (n < nn) ? __expf(v[i] - m) : 0.f;
        v[i] = e;
        s += e;
    }
    #pragma unroll
    for (int o = 16; o > 0; o >>= 1)
        s += __shfl_xor_sync(0xffffffffu, s, o);
    if ((tid & 31) == 0) reds[tid >> 5] = s;
    __syncthreads();
    {
        float t = 0.f;
        #pragma unroll
        for (int w = 0; w < 8; w++) t += reds[w];
        s = t;
    }

    const float inv = 1.f / s;
    float* prow = prob + (size_t)bq * Ns;
    #pragma unroll
    for (int i = 0; i < 64; i++) prow[tid + i * 256] = v[i] * inv;
}

// ---------------------------------------------------------------------------
// Kernel 3: res[b][q][d] = sum_n P[b][q][n] * A[b][n][d]   (split-K + atomics)
// grid (Bsz, 32): each block does K-chunk of 512 n's. block 256.
// ---------------------------------------------------------------------------
__global__ void k_res(const float* __restrict__ P,
                      const float* __restrict__ A,
                      float* __restrict__ res) {
    const int b     = blockIdx.x;
    const int kbase = blockIdx.y * 512;

    __shared__ __align__(16) float sP[32][68];     // [k][q]
    __shared__ __align__(16) float sA2[32][132];   // [k][d]

    const int tid = threadIdx.x;
    const int ty  = tid >> 4;
    const int tx  = tid & 15;
    const int qb  = ty * 4;
    const int db  = tx * 8;

    float acc[4][8];
    #pragma unroll
    for (int i = 0; i < 4; i++)
        #pragma unroll
        for (int j = 0; j < 8; j++) acc[i][j] = 0.f;

    const float* pbase = P + (size_t)b * Qs * Ns;
    const float* abase = A + (size_t)b * Ns * Ds;

    for (int kt = 0; kt < 16; kt++) {
        const int kk = kbase + kt * 32;
        // Load P tile: 64 rows(q) x 32 cols(k), transposed into sP[k][q]
        #pragma unroll
        for (int t = 0; t < 2; t++) {
            int f   = tid + t * 256;
            int row = f >> 3;              // q: 0..63
            int c4  = f & 7;
            float4 v = *(const float4*)(pbase + (size_t)row * Ns + kk + c4 * 4);
            sP[c4 * 4 + 0][row] = v.x;
            sP[c4 * 4 + 1][row] = v.y;
            sP[c4 * 4 + 2][row] = v.z;
            sP[c4 * 4 + 3][row] = v.w;
        }
        // Load A tile: 32 rows(k=n) x 128 cols(d), natural into sA2[k][d]
        #pragma unroll
        for (int t = 0; t < 4; t++) {
            int f   = tid + t * 256;       // 0..1023 float4s
            int row = f >> 5;              // k: 0..31
            int c4  = f & 31;              // 0..31
            float4 v = *(const float4*)(abase + (size_t)(kk + row) * Ds + c4 * 4);
            *(float4*)&sA2[row][c4 * 4] = v;
        }
        __syncthreads();

        #pragma unroll
        for (int k = 0; k < 32; k++) {
            float4 ap = *(const float4*)&sP[k][qb];
            float4 a0 = *(const float4*)&sA2[k][db];
            float4 a1 = *(const float4*)&sA2[k][db + 4];
            float pr[4] = {ap.x, ap.y, ap.z, ap.w};
            float ar[8] = {a0.x, a0.y, a0.z, a0.w, a1.x, a1.y, a1.z, a1.w};
            #pragma unroll
            for (int i = 0; i < 4; i++)
                #pragma unroll
                for (int j = 0; j < 8; j++)
                    acc[i][j] = fmaf(pr[i], ar[j], acc[i][j]);
        }
        __syncthreads();
    }

    float* rbase = res + ((size_t)b * Qs + qb) * Ds + db;
    #pragma unroll
    for (int i = 0; i < 4; i++)
        #pragma unroll
        for (int j = 0; j < 8; j++)
            atomicAdd(rbase + (size_t)i * Ds + j, acc[i][j]);
}

// ---------------------------------------------------------------------------
extern "C" void kernel_launch(void* const* d_in, const int* in_sizes, int n_in,
                              void* d_out, int out_size) {
    const float* qv = (const float*)d_in[0];
    const float* A  = (const float*)d_in[1];
    const int*   nn = (const int*)d_in[2];

    float* out_res  = (float*)d_out;                        // [B,Q,D]
    float* out_soft = out_res  + (size_t)Bsz * Qs * Ds;     // [B,Q,N]
    float* out_log  = out_soft + (size_t)Bsz * Qs * Ns;     // [B,Q,N]

    cudaMemsetAsync(out_res, 0, (size_t)Bsz * Qs * Ds * sizeof(float));

    k_logits<<<dim3(Ns / 128, Bsz), 256>>>(qv, A, out_log);
    k_softmax<<<Bsz * Qs, 256>>>(out_log, nn, out_soft);
    k_res<<<dim3(Bsz, 32), 256>>>(out_soft, A, out_res);
}

// round 3
// speedup vs baseline: 1.6985x; 1.6985x over previous
#include <cuda_runtime.h>
#include <cuda_bf16.h>
#include <cstdint>
#include <math.h>

#define Bsz 16
#define Qs  64
#define Ns  16384
#define Ds  128

// ============================================================================
// helpers
// ============================================================================
__device__ __forceinline__ uint32_t smem_u32(const void* p) {
    uint32_t a;
    asm("{ .reg .u64 t; cvta.to.shared.u64 t, %1; cvt.u32.u64 %0, t; }"
        : "=r"(a) : "l"(p));
    return a;
}

__device__ __forceinline__ void ldm4(uint32_t& r0, uint32_t& r1, uint32_t& r2,
                                     uint32_t& r3, uint32_t addr) {
    asm volatile("ldmatrix.sync.aligned.m8n8.x4.shared.b16 {%0,%1,%2,%3}, [%4];"
                 : "=r"(r0), "=r"(r1), "=r"(r2), "=r"(r3) : "r"(addr));
}
__device__ __forceinline__ void ldm4t(uint32_t& r0, uint32_t& r1, uint32_t& r2,
                                      uint32_t& r3, uint32_t addr) {
    asm volatile("ldmatrix.sync.aligned.m8n8.x4.trans.shared.b16 {%0,%1,%2,%3}, [%4];"
                 : "=r"(r0), "=r"(r1), "=r"(r2), "=r"(r3) : "r"(addr));
}
__device__ __forceinline__ void mma_bf16(float* c, const uint32_t* a,
                                         uint32_t b0, uint32_t b1) {
    asm volatile(
        "mma.sync.aligned.m16n8k16.row.col.f32.bf16.bf16.f32 "
        "{%0,%1,%2,%3}, {%4,%5,%6,%7}, {%8,%9}, {%0,%1,%2,%3};"
        : "+f"(c[0]), "+f"(c[1]), "+f"(c[2]), "+f"(c[3])
        : "r"(a[0]), "r"(a[1]), "r"(a[2]), "r"(a[3]), "r"(b0), "r"(b1));
}

// split fp32 float4 -> bf16 hi (8B) + bf16 lo (8B)
__device__ __forceinline__ void cvt_split(char* hi, char* lo, float4 v) {
    __nv_bfloat16 h0 = __float2bfloat16(v.x);
    __nv_bfloat16 h1 = __float2bfloat16(v.y);
    __nv_bfloat16 h2 = __float2bfloat16(v.z);
    __nv_bfloat16 h3 = __float2bfloat16(v.w);
    __nv_bfloat16 g0 = __float2bfloat16(v.x - __bfloat162float(h0));
    __nv_bfloat16 g1 = __float2bfloat16(v.y - __bfloat162float(h1));
    __nv_bfloat16 g2 = __float2bfloat16(v.z - __bfloat162float(h2));
    __nv_bfloat16 g3 = __float2bfloat16(v.w - __bfloat162float(h3));
    uint2 hp, lp;
    hp.x = (uint32_t)__bfloat16_as_ushort(h0) | ((uint32_t)__bfloat16_as_ushort(h1) << 16);
    hp.y = (uint32_t)__bfloat16_as_ushort(h2) | ((uint32_t)__bfloat16_as_ushort(h3) << 16);
    lp.x = (uint32_t)__bfloat16_as_ushort(g0) | ((uint32_t)__bfloat16_as_ushort(g1) << 16);
    lp.y = (uint32_t)__bfloat16_as_ushort(g2) | ((uint32_t)__bfloat16_as_ushort(g3) << 16);
    *(uint2*)hi = hp;
    *(uint2*)lo = lp;
}

// ============================================================================
// Kernel 1: logits[b][q][n0+i] = A_tile[128n x 128d] @ Q[64q x 128d]^T
// bf16 3-pass fp32 emulation on mma.sync m16n8k16.
// smem tiles row-major, 128+8 bf16 stride (272B rows, conflict-free ldmatrix).
// ============================================================================
static constexpr int L_AHI = 0;
static constexpr int L_ALO = 34816;             // 128*136*2
static constexpr int L_QHI = 69632;
static constexpr int L_QLO = 87040;             // + 64*136*2
static constexpr int L_TOTAL = 104448;

__global__ void __launch_bounds__(256, 1)
k_logits_mma(const float* __restrict__ qv, const float* __restrict__ A,
             float* __restrict__ logits) {
    extern __shared__ char sm[];
    const int tid = threadIdx.x;
    const int b = blockIdx.y, n0 = blockIdx.x * 128;

    // ---- load + split A tile [128n x 128d] ----
    const float* ab = A + ((size_t)b * Ns + n0) * Ds;
    #pragma unroll 4
    for (int i = 0; i < 16; i++) {
        int f = tid + i * 256;
        int row = f >> 5, c4 = f & 31;
        float4 v = *(const float4*)(ab + (size_t)row * Ds + c4 * 4);
        int off = (row * 136 + c4 * 4) * 2;
        cvt_split(sm + L_AHI + off, sm + L_ALO + off, v);
    }
    // ---- load + split Q tile [64q x 128d] ----
    const float* qb = qv + (size_t)b * Qs * Ds;
    #pragma unroll 4
    for (int i = 0; i < 8; i++) {
        int f = tid + i * 256;
        int row = f >> 5, c4 = f & 31;
        float4 v = *(const float4*)(qb + (size_t)row * Ds + c4 * 4);
        int off = (row * 136 + c4 * 4) * 2;
        cvt_split(sm + L_QHI + off, sm + L_QLO + off, v);
    }
    __syncthreads();

    const int wid = tid >> 5, lane = tid & 31;
    const int wm = wid & 3;        // n dim: 4 warps x 32
    const int wq = wid >> 2;       // q dim: 2 warps x 32

    float acc[2][4][4];
    #pragma unroll
    for (int mi = 0; mi < 2; mi++)
        #pragma unroll
        for (int ni = 0; ni < 4; ni++)
            #pragma unroll
            for (int r = 0; r < 4; r++) acc[mi][ni][r] = 0.f;

    const uint32_t sb = smem_u32(sm);
    const int aoff[3] = { L_AHI, L_AHI, L_ALO };
    const int qoff[3] = { L_QHI, L_QLO, L_QHI };

    // per-lane intra-tile offsets (bytes)
    const uint32_t a_row = (uint32_t)(wm * 32 + (lane & 15));
    const uint32_t a_kb  = (uint32_t)(((lane >> 4) << 3) * 2);
    const uint32_t q_row0 = (uint32_t)(wq * 32 + ((lane >> 4) << 3) + (lane & 7));
    const uint32_t q_kb  = (uint32_t)((((lane >> 3) & 1) << 3) * 2);

    #pragma unroll
    for (int p = 0; p < 3; p++) {
        const uint32_t abase = sb + aoff[p] + a_row * 272 + a_kb;
        const uint32_t qbase = sb + qoff[p] + q_row0 * 272 + q_kb;
        #pragma unroll
        for (int k = 0; k < 8; k++) {
            uint32_t af[2][4];
            ldm4(af[0][0], af[0][1], af[0][2], af[0][3], abase + k * 32);
            ldm4(af[1][0], af[1][1], af[1][2], af[1][3], abase + 16 * 272 + k * 32);
            uint32_t bf[4][2];
            {
                uint32_t r0, r1, r2, r3;
                ldm4(r0, r1, r2, r3, qbase + k * 32);
                bf[0][0] = r0; bf[0][1] = r1; bf[1][0] = r2; bf[1][1] = r3;
                ldm4(r0, r1, r2, r3, qbase + 16 * 272 + k * 32);
                bf[2][0] = r0; bf[2][1] = r1; bf[3][0] = r2; bf[3][1] = r3;
            }
            #pragma unroll
            for (int mi = 0; mi < 2; mi++)
                #pragma unroll
                for (int ni = 0; ni < 4; ni++)
                    mma_bf16(acc[mi][ni], af[mi], bf[ni][0], bf[ni][1]);
        }
    }
    __syncthreads();

    // ---- stage D to smem [q][n], stride 132 fp32, then coalesced store ----
    float* sD = (float*)sm;
    const int group = lane >> 2, tc = lane & 3;
    #pragma unroll
    for (int mi = 0; mi < 2; mi++)
        #pragma unroll
        for (int ni = 0; ni < 4; ni++)
            #pragma unroll
            for (int r = 0; r < 4; r++) {
                int nl = wm * 32 + mi * 16 + group + ((r >> 1) << 3);
                int ql = wq * 32 + ni * 8 + (tc << 1) + (r & 1);
                sD[ql * 132 + nl] = acc[mi][ni][r];
            }
    __syncthreads();

    float* lb = logits + (size_t)b * Qs * Ns + n0;
    #pragma unroll
    for (int i = 0; i < 8; i++) {
        int f = tid + i * 256;
        int q = f >> 5, c4 = f & 31;
        float4 v = *(const float4*)&sD[q * 132 + c4 * 4];
        *(float4*)(lb + (size_t)q * Ns + c4 * 4) = v;
    }
}

// ============================================================================
// Kernel 2: masked softmax over N per (b,q) row.
// ============================================================================
__global__ void k_softmax(const float* __restrict__ logits,
                          const int* __restrict__ node_nums,
                          float* __restrict__ prob) {
    const int bq  = blockIdx.x;
    const int b   = bq >> 6;
    const int nn  = node_nums[b];
    const int tid = threadIdx.x;

    const float* row = logits + (size_t)bq * Ns;
    float v[64];
    #pragma unroll
    for (int i = 0; i < 64; i++) v[i] = row[tid + i * 256];

    float m = -INFINITY;
    #pragma unroll
    for (int i = 0; i < 64; i++) {
        int n = tid + i * 256;
        if (n < nn) m = fmaxf(m, v[i]);
    }
    __shared__ float redm[8];
    __shared__ float reds[8];
    #pragma unroll
    for (int o = 16; o > 0; o >>= 1)
        m = fmaxf(m, __shfl_xor_sync(0xffffffffu, m, o));
    if ((tid & 31) == 0) redm[tid >> 5] = m;
    __syncthreads();
    {
        float t = redm[0];
        #pragma unroll
        for (int w = 1; w < 8; w++) t = fmaxf(t, redm[w]);
        m = t;
    }

    float s = 0.f;
    #pragma unroll
    for (int i = 0; i < 64; i++) {
        int n = tid + i * 256;
        float e = (n < nn) ? __expf(v[i] - m) : 0.f;
        v[i] = e;
        s += e;
    }
    #pragma unroll
    for (int o = 16; o > 0; o >>= 1)
        s += __shfl_xor_sync(0xffffffffu, s, o);
    if ((tid & 31) == 0) reds[tid >> 5] = s;
    __syncthreads();
    {
        float t = 0.f;
        #pragma unroll
        for (int w = 0; w < 8; w++) t += reds[w];
        s = t;
    }

    const float inv = 1.f / s;
    float* prow = prob + (size_t)bq * Ns;
    #pragma unroll
    for (int i = 0; i < 64; i++) prow[tid + i * 256] = v[i] * inv;
}

// ============================================================================
// Kernel 3: res[b][q][d] = sum_n P[b][q][n] * A[b][n][d]
// bf16 3-pass mma.sync, split-K (16 chunks of 1024) + atomicAdd epilogue.
// P operand: [q][n] row-major; A operand via ldmatrix.trans on [n][d] tiles.
// ============================================================================
static constexpr int R_PHI = 0;
static constexpr int R_PLO = 9216;              // 64*72*2
static constexpr int R_AHI = 18432;
static constexpr int R_ALO = 35840;             // + 64*136*2
static constexpr int R_TOTAL = 53248;

__global__ void __launch_bounds__(256, 1)
k_res_mma(const float* __restrict__ P, const float* __restrict__ A,
          float* __restrict__ res) {
    extern __shared__ char sm[];
    const int b = blockIdx.x;
    const int kbase = blockIdx.y * 1024;
    const int tid = threadIdx.x;
    const int wid = tid >> 5, lane = tid & 31;
    const int wm = wid & 1;        // q dim: 2 warps x 32
    const int wd = wid >> 1;       // d dim: 4 warps x 32

    float acc[2][4][4];
    #pragma unroll
    for (int mi = 0; mi < 2; mi++)
        #pragma unroll
        for (int ni = 0; ni < 4; ni++)
            #pragma unroll
            for (int r = 0; r < 4; r++) acc[mi][ni][r] = 0.f;

    const float* pbase = P + (size_t)b * Qs * Ns;
    const float* abase = A + (size_t)b * Ns * Ds;
    const uint32_t sb = smem_u32(sm);

    const int poff[3] = { R_PHI, R_PHI, R_PLO };
    const int aoff[3] = { R_AHI, R_ALO, R_AHI };

    const uint32_t p_row = (uint32_t)(wm * 32 + (lane & 15));
    const uint32_t p_kb  = (uint32_t)(((lane >> 4) << 3) * 2);
    const uint32_t a_krow0 = (uint32_t)((((lane >> 3) & 1) << 3) + (lane & 7));
    const uint32_t a_dcol  = (uint32_t)((wd * 32 + ((lane >> 4) << 3)) * 2);

    for (int kt = 0; kt < 16; kt++) {
        const int kk = kbase + kt * 64;
        // load P tile [64q x 64n]
        #pragma unroll
        for (int i = 0; i < 4; i++) {
            int f = tid + i * 256;
            int q = f >> 4, c4 = f & 15;
            float4 v = *(const float4*)(pbase + (size_t)q * Ns + kk + c4 * 4);
            int off = (q * 72 + c4 * 4) * 2;
            cvt_split(sm + R_PHI + off, sm + R_PLO + off, v);
        }
        // load A tile [64n x 128d]
        #pragma unroll
        for (int i = 0; i < 8; i++) {
            int f = tid + i * 256;
            int n = f >> 5, c4 = f & 31;
            float4 v = *(const float4*)(abase + (size_t)(kk + n) * Ds + c4 * 4);
            int off = (n * 136 + c4 * 4) * 2;
            cvt_split(sm + R_AHI + off, sm + R_ALO + off, v);
        }
        __syncthreads();

        #pragma unroll
        for (int p = 0; p < 3; p++) {
            const uint32_t pb_ = sb + poff[p] + p_row * 144 + p_kb;
            const uint32_t ab_ = sb + aoff[p] + a_krow0 * 272 + a_dcol;
            #pragma unroll
            for (int k = 0; k < 4; k++) {
                uint32_t af[2][4];
                ldm4(af[0][0], af[0][1], af[0][2], af[0][3], pb_ + k * 32);
                ldm4(af[1][0], af[1][1], af[1][2], af[1][3], pb_ + 16 * 144 + k * 32);
                uint32_t bfr[4][2];
                {
                    uint32_t r0, r1, r2, r3;
                    ldm4t(r0, r1, r2, r3, ab_ + k * 16 * 272);
                    bfr[0][0] = r0; bfr[0][1] = r1; bfr[1][0] = r2; bfr[1][1] = r3;
                    ldm4t(r0, r1, r2, r3, ab_ + k * 16 * 272 + 16 * 2);
                    bfr[2][0] = r0; bfr[2][1] = r1; bfr[3][0] = r2; bfr[3][1] = r3;
                }
                #pragma unroll
                for (int mi = 0; mi < 2; mi++)
                    #pragma unroll
                    for (int ni = 0; ni < 4; ni++)
                        mma_bf16(acc[mi][ni], af[mi], bfr[ni][0], bfr[ni][1]);
            }
        }
        __syncthreads();
    }

    // epilogue: atomic accumulate into res[b][q][d]
    const int group = lane >> 2, tc = lane & 3;
    float* rb = res + (size_t)b * Qs * Ds;
    #pragma unroll
    for (int mi = 0; mi < 2; mi++)
        #pragma unroll
        for (int ni = 0; ni < 4; ni++)
            #pragma unroll
            for (int r = 0; r < 4; r++) {
                int q = wm * 32 + mi * 16 + group + ((r >> 1) << 3);
                int d = wd * 32 + ni * 8 + (tc << 1) + (r & 1);
                atomicAdd(rb + (size_t)q * Ds + d, acc[mi][ni][r]);
            }
}

// ---------------------------------------------------------------------------
extern "C" void kernel_launch(void* const* d_in, const int* in_sizes, int n_in,
                              void* d_out, int out_size) {
    const float* qv = (const float*)d_in[0];
    const float* A  = (const float*)d_in[1];
    const int*   nn = (const int*)d_in[2];

    float* out_res  = (float*)d_out;                        // [B,Q,D]
    float* out_soft = out_res  + (size_t)Bsz * Qs * Ds;     // [B,Q,N]
    float* out_log  = out_soft + (size_t)Bsz * Qs * Ns;     // [B,Q,N]

    cudaMemsetAsync(out_res, 0, (size_t)Bsz * Qs * Ds * sizeof(float));

    cudaFuncSetAttribute(k_logits_mma,
                         cudaFuncAttributeMaxDynamicSharedMemorySize, L_TOTAL);
    cudaFuncSetAttribute(k_res_mma,
                         cudaFuncAttributeMaxDynamicSharedMemorySize, R_TOTAL);

    k_logits_mma<<<dim3(Ns / 128, Bsz), 256, L_TOTAL>>>(qv, A, out_log);
    k_softmax<<<Bsz * Qs, 256>>>(out_log, nn, out_soft);
    k_res_mma<<<dim3(Bsz, 16), 256, R_TOTAL>>>(out_soft, A, out_res);
}

// round 4
// speedup vs baseline: 2.3776x; 1.3999x over previous
#include <cuda_runtime.h>
#include <cuda_bf16.h>
#include <cstdint>
#include <math.h>

#define Bsz 16
#define Qs  64
#define Ns  16384
#define Ds  128

// ============================================================================
// helpers
// ============================================================================
__device__ __forceinline__ uint32_t smem_u32(const void* p) {
    uint32_t a;
    asm("{ .reg .u64 t; cvta.to.shared.u64 t, %1; cvt.u32.u64 %0, t; }"
        : "=r"(a) : "l"(p));
    return a;
}

__device__ __forceinline__ void ldm4(uint32_t& r0, uint32_t& r1, uint32_t& r2,
                                     uint32_t& r3, uint32_t addr) {
    asm volatile("ldmatrix.sync.aligned.m8n8.x4.shared.b16 {%0,%1,%2,%3}, [%4];"
                 : "=r"(r0), "=r"(r1), "=r"(r2), "=r"(r3) : "r"(addr));
}
__device__ __forceinline__ void ldm4t(uint32_t& r0, uint32_t& r1, uint32_t& r2,
                                      uint32_t& r3, uint32_t addr) {
    asm volatile("ldmatrix.sync.aligned.m8n8.x4.trans.shared.b16 {%0,%1,%2,%3}, [%4];"
                 : "=r"(r0), "=r"(r1), "=r"(r2), "=r"(r3) : "r"(addr));
}
__device__ __forceinline__ void mma_bf16(float* c, const uint32_t* a,
                                         uint32_t b0, uint32_t b1) {
    asm volatile(
        "mma.sync.aligned.m16n8k16.row.col.f32.bf16.bf16.f32 "
        "{%0,%1,%2,%3}, {%4,%5,%6,%7}, {%8,%9}, {%0,%1,%2,%3};"
        : "+f"(c[0]), "+f"(c[1]), "+f"(c[2]), "+f"(c[3])
        : "r"(a[0]), "r"(a[1]), "r"(a[2]), "r"(a[3]), "r"(b0), "r"(b1));
}

// split fp32 float4 -> bf16 hi (8B) + bf16 lo (8B)
__device__ __forceinline__ void cvt_split(char* hi, char* lo, float4 v) {
    __nv_bfloat16 h0 = __float2bfloat16(v.x);
    __nv_bfloat16 h1 = __float2bfloat16(v.y);
    __nv_bfloat16 h2 = __float2bfloat16(v.z);
    __nv_bfloat16 h3 = __float2bfloat16(v.w);
    __nv_bfloat16 g0 = __float2bfloat16(v.x - __bfloat162float(h0));
    __nv_bfloat16 g1 = __float2bfloat16(v.y - __bfloat162float(h1));
    __nv_bfloat16 g2 = __float2bfloat16(v.z - __bfloat162float(h2));
    __nv_bfloat16 g3 = __float2bfloat16(v.w - __bfloat162float(h3));
    uint2 hp, lp;
    hp.x = (uint32_t)__bfloat16_as_ushort(h0) | ((uint32_t)__bfloat16_as_ushort(h1) << 16);
    hp.y = (uint32_t)__bfloat16_as_ushort(h2) | ((uint32_t)__bfloat16_as_ushort(h3) << 16);
    lp.x = (uint32_t)__bfloat16_as_ushort(g0) | ((uint32_t)__bfloat16_as_ushort(g1) << 16);
    lp.y = (uint32_t)__bfloat16_as_ushort(g2) | ((uint32_t)__bfloat16_as_ushort(g3) << 16);
    *(uint2*)hi = hp;
    *(uint2*)lo = lp;
}

// ============================================================================
// Kernel 1: logits[b][q][n0+i] = A_tile[128n x 128d] @ Q[64q x 128d]^T
// bf16 3-pass fp32 emulation on mma.sync m16n8k16.
// 2 CTAs/SM co-residency + MLP-8 prefetch loads.
// ============================================================================
static constexpr int L_AHI = 0;
static constexpr int L_ALO = 34816;             // 128*136*2
static constexpr int L_QHI = 69632;
static constexpr int L_QLO = 87040;             // + 64*136*2
static constexpr int L_TOTAL = 104448;

__global__ void __launch_bounds__(256, 2)
k_logits_mma(const float* __restrict__ qv, const float* __restrict__ A,
             float* __restrict__ logits) {
    extern __shared__ char sm[];
    const int tid = threadIdx.x;
    const int b = blockIdx.y, n0 = blockIdx.x * 128;

    // ---- load + split A tile [128n x 128d], MLP-8 prefetch ----
    const float* ab = A + ((size_t)b * Ns + n0) * Ds;
    #pragma unroll
    for (int g = 0; g < 2; g++) {
        float4 va[8];
        #pragma unroll
        for (int i = 0; i < 8; i++) {
            int f = tid + (g * 8 + i) * 256;
            va[i] = *(const float4*)(ab + (size_t)(f >> 5) * Ds + (f & 31) * 4);
        }
        #pragma unroll
        for (int i = 0; i < 8; i++) {
            int f = tid + (g * 8 + i) * 256;
            int off = ((f >> 5) * 136 + (f & 31) * 4) * 2;
            cvt_split(sm + L_AHI + off, sm + L_ALO + off, va[i]);
        }
    }
    // ---- load + split Q tile [64q x 128d], MLP-8 ----
    const float* qb = qv + (size_t)b * Qs * Ds;
    {
        float4 vq[8];
        #pragma unroll
        for (int i = 0; i < 8; i++) {
            int f = tid + i * 256;
            vq[i] = *(const float4*)(qb + (size_t)(f >> 5) * Ds + (f & 31) * 4);
        }
        #pragma unroll
        for (int i = 0; i < 8; i++) {
            int f = tid + i * 256;
            int off = ((f >> 5) * 136 + (f & 31) * 4) * 2;
            cvt_split(sm + L_QHI + off, sm + L_QLO + off, vq[i]);
        }
    }
    __syncthreads();

    const int wid = tid >> 5, lane = tid & 31;
    const int wm = wid & 3;        // n dim: 4 warps x 32
    const int wq = wid >> 2;       // q dim: 2 warps x 32

    float acc[2][4][4];
    #pragma unroll
    for (int mi = 0; mi < 2; mi++)
        #pragma unroll
        for (int ni = 0; ni < 4; ni++)
            #pragma unroll
            for (int r = 0; r < 4; r++) acc[mi][ni][r] = 0.f;

    const uint32_t sb = smem_u32(sm);
    const int aoff[3] = { L_AHI, L_AHI, L_ALO };
    const int qoff[3] = { L_QHI, L_QLO, L_QHI };

    const uint32_t a_row = (uint32_t)(wm * 32 + (lane & 15));
    const uint32_t a_kb  = (uint32_t)(((lane >> 4) << 3) * 2);
    const uint32_t q_row0 = (uint32_t)(wq * 32 + ((lane >> 4) << 3) + (lane & 7));
    const uint32_t q_kb  = (uint32_t)((((lane >> 3) & 1) << 3) * 2);

    #pragma unroll
    for (int p = 0; p < 3; p++) {
        const uint32_t abase = sb + aoff[p] + a_row * 272 + a_kb;
        const uint32_t qbase = sb + qoff[p] + q_row0 * 272 + q_kb;
        #pragma unroll
        for (int k = 0; k < 8; k++) {
            uint32_t af[2][4];
            ldm4(af[0][0], af[0][1], af[0][2], af[0][3], abase + k * 32);
            ldm4(af[1][0], af[1][1], af[1][2], af[1][3], abase + 16 * 272 + k * 32);
            uint32_t bf[4][2];
            {
                uint32_t r0, r1, r2, r3;
                ldm4(r0, r1, r2, r3, qbase + k * 32);
                bf[0][0] = r0; bf[0][1] = r1; bf[1][0] = r2; bf[1][1] = r3;
                ldm4(r0, r1, r2, r3, qbase + 16 * 272 + k * 32);
                bf[2][0] = r0; bf[2][1] = r1; bf[3][0] = r2; bf[3][1] = r3;
            }
            #pragma unroll
            for (int mi = 0; mi < 2; mi++)
                #pragma unroll
                for (int ni = 0; ni < 4; ni++)
                    mma_bf16(acc[mi][ni], af[mi], bf[ni][0], bf[ni][1]);
        }
    }
    __syncthreads();

    // ---- stage D to smem [q][n], stride 132 fp32, then coalesced store ----
    float* sD = (float*)sm;
    const int group = lane >> 2, tc = lane & 3;
    #pragma unroll
    for (int mi = 0; mi < 2; mi++)
        #pragma unroll
        for (int ni = 0; ni < 4; ni++)
            #pragma unroll
            for (int r = 0; r < 4; r++) {
                int nl = wm * 32 + mi * 16 + group + ((r >> 1) << 3);
                int ql = wq * 32 + ni * 8 + (tc << 1) + (r & 1);
                sD[ql * 132 + nl] = acc[mi][ni][r];
            }
    __syncthreads();

    float* lb = logits + (size_t)b * Qs * Ns + n0;
    #pragma unroll
    for (int i = 0; i < 8; i++) {
        int f = tid + i * 256;
        int q = f >> 5, c4 = f & 31;
        float4 v = *(const float4*)&sD[q * 132 + c4 * 4];
        *(float4*)(lb + (size_t)q * Ns + c4 * 4) = v;
    }
}

// ============================================================================
// Kernel 2: masked softmax over N per (b,q) row.
// ============================================================================
__global__ void k_softmax(const float* __restrict__ logits,
                          const int* __restrict__ node_nums,
                          float* __restrict__ prob) {
    const int bq  = blockIdx.x;
    const int b   = bq >> 6;
    const int nn  = node_nums[b];
    const int tid = threadIdx.x;

    const float* row = logits + (size_t)bq * Ns;
    float v[64];
    #pragma unroll
    for (int i = 0; i < 64; i++) v[i] = row[tid + i * 256];

    float m = -INFINITY;
    #pragma unroll
    for (int i = 0; i < 64; i++) {
        int n = tid + i * 256;
        if (n < nn) m = fmaxf(m, v[i]);
    }
    __shared__ float redm[8];
    __shared__ float reds[8];
    #pragma unroll
    for (int o = 16; o > 0; o >>= 1)
        m = fmaxf(m, __shfl_xor_sync(0xffffffffu, m, o));
    if ((tid & 31) == 0) redm[tid >> 5] = m;
    __syncthreads();
    {
        float t = redm[0];
        #pragma unroll
        for (int w = 1; w < 8; w++) t = fmaxf(t, redm[w]);
        m = t;
    }

    float s = 0.f;
    #pragma unroll
    for (int i = 0; i < 64; i++) {
        int n = tid + i * 256;
        float e = (n < nn) ? __expf(v[i] - m) : 0.f;
        v[i] = e;
        s += e;
    }
    #pragma unroll
    for (int o = 16; o > 0; o >>= 1)
        s += __shfl_xor_sync(0xffffffffu, s, o);
    if ((tid & 31) == 0) reds[tid >> 5] = s;
    __syncthreads();
    {
        float t = 0.f;
        #pragma unroll
        for (int w = 0; w < 8; w++) t += reds[w];
        s = t;
    }

    const float inv = 1.f / s;
    float* prow = prob + (size_t)bq * Ns;
    #pragma unroll
    for (int i = 0; i < 64; i++) prow[tid + i * 256] = v[i] * inv;
}

// ============================================================================
// Kernel 3: res[b][q][d] = sum_n P[b][q][n] * A[b][n][d]
// bf16 3-pass mma.sync, split-K (32 chunks of 512) + atomicAdd epilogue.
// 2 CTAs/SM co-residency + prefetch loads.
// ============================================================================
static constexpr int R_PHI = 0;
static constexpr int R_PLO = 9216;              // 64*72*2
static constexpr int R_AHI = 18432;
static constexpr int R_ALO = 35840;             // + 64*136*2
static constexpr int R_TOTAL = 53248;

__global__ void __launch_bounds__(256, 2)
k_res_mma(const float* __restrict__ P, const float* __restrict__ A,
          float* __restrict__ res) {
    extern __shared__ char sm[];
    const int b = blockIdx.x;
    const int kbase = blockIdx.y * 512;
    const int tid = threadIdx.x;
    const int wid = tid >> 5, lane = tid & 31;
    const int wm = wid & 1;        // q dim: 2 warps x 32
    const int wd = wid >> 1;       // d dim: 4 warps x 32

    float acc[2][4][4];
    #pragma unroll
    for (int mi = 0; mi < 2; mi++)
        #pragma unroll
        for (int ni = 0; ni < 4; ni++)
            #pragma unroll
            for (int r = 0; r < 4; r++) acc[mi][ni][r] = 0.f;

    const float* pbase = P + (size_t)b * Qs * Ns;
    const float* abase = A + (size_t)b * Ns * Ds;
    const uint32_t sb = smem_u32(sm);

    const int poff[3] = { R_PHI, R_PHI, R_PLO };
    const int aoff[3] = { R_AHI, R_ALO, R_AHI };

    const uint32_t p_row = (uint32_t)(wm * 32 + (lane & 15));
    const uint32_t p_kb  = (uint32_t)(((lane >> 4) << 3) * 2);
    const uint32_t a_krow0 = (uint32_t)((((lane >> 3) & 1) << 3) + (lane & 7));
    const uint32_t a_dcol  = (uint32_t)((wd * 32 + ((lane >> 4) << 3)) * 2);

    for (int kt = 0; kt < 8; kt++) {
        const int kk = kbase + kt * 64;
        // prefetch P tile [64q x 64n] (4 float4) + A tile first half (4 float4)
        {
            float4 vp[4], va[4];
            #pragma unroll
            for (int i = 0; i < 4; i++) {
                int f = tid + i * 256;
                vp[i] = *(const float4*)(pbase + (size_t)(f >> 4) * Ns + kk + (f & 15) * 4);
            }
            #pragma unroll
            for (int i = 0; i < 4; i++) {
                int f = tid + i * 256;
                va[i] = *(const float4*)(abase + (size_t)(kk + (f >> 5)) * Ds + (f & 31) * 4);
            }
            #pragma unroll
            for (int i = 0; i < 4; i++) {
                int f = tid + i * 256;
                int off = ((f >> 4) * 72 + (f & 15) * 4) * 2;
                cvt_split(sm + R_PHI + off, sm + R_PLO + off, vp[i]);
            }
            #pragma unroll
            for (int i = 0; i < 4; i++) {
                int f = tid + i * 256;
                int off = ((f >> 5) * 136 + (f & 31) * 4) * 2;
                cvt_split(sm + R_AHI + off, sm + R_ALO + off, va[i]);
            }
        }
        {
            float4 va[4];
            #pragma unroll
            for (int i = 0; i < 4; i++) {
                int f = tid + (4 + i) * 256;
                va[i] = *(const float4*)(abase + (size_t)(kk + (f >> 5)) * Ds + (f & 31) * 4);
            }
            #pragma unroll
            for (int i = 0; i < 4; i++) {
                int f = tid + (4 + i) * 256;
                int off = ((f >> 5) * 136 + (f & 31) * 4) * 2;
                cvt_split(sm + R_AHI + off, sm + R_ALO + off, va[i]);
            }
        }
        __syncthreads();

        #pragma unroll
        for (int p = 0; p < 3; p++) {
            const uint32_t pb_ = sb + poff[p] + p_row * 144 + p_kb;
            const uint32_t ab_ = sb + aoff[p] + a_krow0 * 272 + a_dcol;
            #pragma unroll
            for (int k = 0; k < 4; k++) {
                uint32_t af[2][4];
                ldm4(af[0][0], af[0][1], af[0][2], af[0][3], pb_ + k * 32);
                ldm4(af[1][0], af[1][1], af[1][2], af[1][3], pb_ + 16 * 144 + k * 32);
                uint32_t bfr[4][2];
                {
                    uint32_t r0, r1, r2, r3;
                    ldm4t(r0, r1, r2, r3, ab_ + k * 16 * 272);
                    bfr[0][0] = r0; bfr[0][1] = r1; bfr[1][0] = r2; bfr[1][1] = r3;
                    ldm4t(r0, r1, r2, r3, ab_ + k * 16 * 272 + 16 * 2);
                    bfr[2][0] = r0; bfr[2][1] = r1; bfr[3][0] = r2; bfr[3][1] = r3;
                }
                #pragma unroll
                for (int mi = 0; mi < 2; mi++)
                    #pragma unroll
                    for (int ni = 0; ni < 4; ni++)
                        mma_bf16(acc[mi][ni], af[mi], bfr[ni][0], bfr[ni][1]);
            }
        }
        __syncthreads();
    }

    // epilogue: atomic accumulate into res[b][q][d]
    const int group = lane >> 2, tc = lane & 3;
    float* rb = res + (size_t)b * Qs * Ds;
    #pragma unroll
    for (int mi = 0; mi < 2; mi++)
        #pragma unroll
        for (int ni = 0; ni < 4; ni++)
            #pragma unroll
            for (int r = 0; r < 4; r++) {
                int q = wm * 32 + mi * 16 + group + ((r >> 1) << 3);
                int d = wd * 32 + ni * 8 + (tc << 1) + (r & 1);
                atomicAdd(rb + (size_t)q * Ds + d, acc[mi][ni][r]);
            }
}

// ---------------------------------------------------------------------------
extern "C" void kernel_launch(void* const* d_in, const int* in_sizes, int n_in,
                              void* d_out, int out_size) {
    const float* qv = (const float*)d_in[0];
    const float* A  = (const float*)d_in[1];
    const int*   nn = (const int*)d_in[2];

    float* out_res  = (float*)d_out;                        // [B,Q,D]
    float* out_soft = out_res  + (size_t)Bsz * Qs * Ds;     // [B,Q,N]
    float* out_log  = out_soft + (size_t)Bsz * Qs * Ns;     // [B,Q,N]

    cudaMemsetAsync(out_res, 0, (size_t)Bsz * Qs * Ds * sizeof(float));

    cudaFuncSetAttribute(k_logits_mma,
                         cudaFuncAttributeMaxDynamicSharedMemorySize, L_TOTAL);
    cudaFuncSetAttribute(k_res_mma,
                         cudaFuncAttributeMaxDynamicSharedMemorySize, R_TOTAL);

    k_logits_mma<<<dim3(Ns / 128, Bsz), 256, L_TOTAL>>>(qv, A, out_log);
    k_softmax<<<Bsz * Qs, 256>>>(out_log, nn, out_soft);
    k_res_mma<<<dim3(Bsz, 32), 256, R_TOTAL>>>(out_soft, A, out_res);
}